// round 13
// baseline (speedup 1.0000x reference)
#include <cuda_runtime.h>
#include <cuda_bf16.h>
#include <cstdint>
#include <math_constants.h>

// ---------------------------------------------------------------------------
// Problem constants
// ---------------------------------------------------------------------------
#define IN_DIM   256
#define OUT_DIM  256
#define NUM_HEADS 4
#define HEAD_DIM  64
#define MAX_SRC  100000
#define MAX_DST  50000
#define MAX_E    300000
#define NBLK_SCAN 64            // >= ceil(ceil(MAX_DST/4)/256) = 49

// ---------------------------------------------------------------------------
// Device-global scratch
// ---------------------------------------------------------------------------
__device__ float g_Q[(size_t)MAX_DST * OUT_DIM];
__device__ float g_K[(size_t)MAX_SRC * OUT_DIM];
__device__ float g_V[(size_t)MAX_SRC * OUT_DIM];
__device__ int   g_cnt[MAX_DST];
__device__ int   g_start[MAX_DST];   // local excl scan; post-scatter = start+deg
__device__ int   g_bsum[NBLK_SCAN];  // per-chunk totals
__device__ int   g_boff[NBLK_SCAN];  // exclusive scan of chunk totals
__device__ int   g_esrc[MAX_E];

// ---------------------------------------------------------------------------
// Helpers
// ---------------------------------------------------------------------------
__device__ __forceinline__ unsigned f2tf32(float f) {
    unsigned u;
    asm("cvt.rna.tf32.f32 %0, %1;" : "=r"(u) : "f"(f));
    return u;
}

__device__ __forceinline__ void mma_tf32(float c[4], const unsigned a[4],
                                         const unsigned b[2]) {
    asm volatile(
        "mma.sync.aligned.m16n8k8.row.col.f32.tf32.tf32.f32 "
        "{%0,%1,%2,%3}, {%4,%5,%6,%7}, {%8,%9}, {%0,%1,%2,%3};"
        : "+f"(c[0]), "+f"(c[1]), "+f"(c[2]), "+f"(c[3])
        : "r"(a[0]), "r"(a[1]), "r"(a[2]), "r"(a[3]), "r"(b[0]), "r"(b[1]));
}

__device__ __forceinline__ void cp16(unsigned dst, const void* src, int sz) {
    asm volatile("cp.async.cg.shared.global [%0], [%1], 16, %2;"
                 :: "r"(dst), "l"(src), "r"(sz));
}
__device__ __forceinline__ void cp_commit() {
    asm volatile("cp.async.commit_group;");
}
__device__ __forceinline__ void cp_wait_all() {
    asm volatile("cp.async.wait_group 0;");
}

// ---------------------------------------------------------------------------
// TF32 GEMM, cp.async double-buffered, optional dual output (K,V share A).
// R10/R12-proven shape: CTA tile 128(M) x 64(N), BK=32, 8 warps 4(M) x 2(N).
// ---------------------------------------------------------------------------
template<bool DUAL>
__global__ __launch_bounds__(256)
void gemm_cpasync(const float* __restrict__ A,
                  const float* __restrict__ W0, const float* __restrict__ b0,
                  float* __restrict__ C0,
                  const float* __restrict__ W1, const float* __restrict__ b1,
                  float* __restrict__ C1, int M)
{
    extern __shared__ __align__(16) unsigned char smraw[];
    const int A_ELE   = 128 * 36;
    const int W_ELE   = 64 * 36;
    const int STG_ELE = A_ELE + (DUAL ? 2 : 1) * W_ELE;

    float*    smf = (float*)smraw;
    unsigned* smu = (unsigned*)smraw;
    const unsigned sm_u32 = (unsigned)__cvta_generic_to_shared(smraw);

    const int bm = blockIdx.x * 128;
    const int bn = blockIdx.y * 64;
    const int t    = threadIdx.x;
    const int warp = t >> 5;
    const int lane = t & 31;
    const int wm   = warp >> 1;
    const int wn   = warp & 1;
    const int g    = lane >> 2;
    const int tg   = lane & 3;

    int ar[4], ac[4];
    #pragma unroll
    for (int i = 0; i < 4; i++) { int idx = t + i * 256; ar[i] = idx >> 3; ac[i] = (idx & 7) * 4; }
    int wr[2], wc[2];
    #pragma unroll
    for (int i = 0; i < 2; i++) { int idx = t + i * 256; wr[i] = idx >> 3; wc[i] = (idx & 7) * 4; }

    float c0[2][4][4] = {};
    float c1[2][4][4] = {};

    auto loadA = [&](int kk, int st) {
        unsigned base = sm_u32 + (unsigned)(st * STG_ELE) * 4u;
        #pragma unroll
        for (int i = 0; i < 4; i++) {
            int row = bm + ar[i];
            const float* src = A + (size_t)(row < M ? row : (M - 1)) * IN_DIM + kk + ac[i];
            cp16(base + (unsigned)(ar[i] * 36 + ac[i]) * 4u, src, (row < M) ? 16 : 0);
        }
        cp_commit();
    };

    uint4 w0reg[2], w1reg[2];
    auto loadW = [&](int kk) {
        #pragma unroll
        for (int i = 0; i < 2; i++) {
            float4 v = *(const float4*)(W0 + (size_t)(bn + wr[i]) * IN_DIM + kk + wc[i]);
            w0reg[i] = make_uint4(f2tf32(v.x), f2tf32(v.y), f2tf32(v.z), f2tf32(v.w));
            if (DUAL) {
                float4 u = *(const float4*)(W1 + (size_t)(bn + wr[i]) * IN_DIM + kk + wc[i]);
                w1reg[i] = make_uint4(f2tf32(u.x), f2tf32(u.y), f2tf32(u.z), f2tf32(u.w));
            }
        }
    };
    auto storeW = [&](int st) {
        unsigned* p0 = smu + st * STG_ELE + A_ELE;
        #pragma unroll
        for (int i = 0; i < 2; i++)
            *(uint4*)(p0 + wr[i] * 36 + wc[i]) = w0reg[i];
        if (DUAL) {
            unsigned* p1 = p0 + W_ELE;
            #pragma unroll
            for (int i = 0; i < 2; i++)
                *(uint4*)(p1 + wr[i] * 36 + wc[i]) = w1reg[i];
        }
    };

    loadA(0, 0);
    loadW(0);
    storeW(0);
    cp_wait_all();
    __syncthreads();

    const int NSTG = IN_DIM / 32;   // 8
    for (int it = 0; it < NSTG; it++) {
        int cur = it & 1, nxt = cur ^ 1;
        if (it + 1 < NSTG) {
            loadA((it + 1) * 32, nxt);
            loadW((it + 1) * 32);
        }

        const float*    Af = smf + cur * STG_ELE;
        const unsigned* B0 = smu + cur * STG_ELE + A_ELE;
        const unsigned* B1 = B0 + W_ELE;
        #pragma unroll
        for (int ks = 0; ks < 32; ks += 8) {
            unsigned a[2][4], b0f[4][2], b1f[4][2];
            #pragma unroll
            for (int mi = 0; mi < 2; mi++) {
                int r = wm * 32 + mi * 16;
                a[mi][0] = f2tf32(Af[(r + g) * 36 + ks + tg]);
                a[mi][1] = f2tf32(Af[(r + g + 8) * 36 + ks + tg]);
                a[mi][2] = f2tf32(Af[(r + g) * 36 + ks + tg + 4]);
                a[mi][3] = f2tf32(Af[(r + g + 8) * 36 + ks + tg + 4]);
            }
            #pragma unroll
            for (int nj = 0; nj < 4; nj++) {
                int r = wn * 32 + nj * 8 + g;
                b0f[nj][0] = B0[r * 36 + ks + tg];
                b0f[nj][1] = B0[r * 36 + ks + tg + 4];
                if (DUAL) {
                    b1f[nj][0] = B1[r * 36 + ks + tg];
                    b1f[nj][1] = B1[r * 36 + ks + tg + 4];
                }
            }
            #pragma unroll
            for (int mi = 0; mi < 2; mi++)
                #pragma unroll
                for (int nj = 0; nj < 4; nj++) {
                    mma_tf32(c0[mi][nj], a[mi], b0f[nj]);
                    if (DUAL) mma_tf32(c1[mi][nj], a[mi], b1f[nj]);
                }
        }

        if (it + 1 < NSTG) storeW(nxt);
        cp_wait_all();
        __syncthreads();
    }

    #pragma unroll
    for (int mi = 0; mi < 2; mi++) {
        int row0 = bm + wm * 32 + mi * 16 + g;
        #pragma unroll
        for (int nj = 0; nj < 4; nj++) {
            int col = bn + wn * 32 + nj * 8 + 2 * tg;
            float bb0 = b0[col], bb1 = b0[col + 1];
            if (row0 < M) {
                C0[(size_t)row0 * OUT_DIM + col]     = c0[mi][nj][0] + bb0;
                C0[(size_t)row0 * OUT_DIM + col + 1] = c0[mi][nj][1] + bb1;
            }
            if (row0 + 8 < M) {
                C0[(size_t)(row0 + 8) * OUT_DIM + col]     = c0[mi][nj][2] + bb0;
                C0[(size_t)(row0 + 8) * OUT_DIM + col + 1] = c0[mi][nj][3] + bb1;
            }
            if (DUAL) {
                float db0 = b1[col], db1 = b1[col + 1];
                if (row0 < M) {
                    C1[(size_t)row0 * OUT_DIM + col]     = c1[mi][nj][0] + db0;
                    C1[(size_t)row0 * OUT_DIM + col + 1] = c1[mi][nj][1] + db1;
                }
                if (row0 + 8 < M) {
                    C1[(size_t)(row0 + 8) * OUT_DIM + col]     = c1[mi][nj][2] + db0;
                    C1[(size_t)(row0 + 8) * OUT_DIM + col + 1] = c1[mi][nj][3] + db1;
                }
            }
        }
    }
}

// ---------------------------------------------------------------------------
// CSR build
// ---------------------------------------------------------------------------
__global__ void histogram_kernel(const int* __restrict__ dst, int E)
{
    int i = blockIdx.x * blockDim.x + threadIdx.x;
    if (i < E) atomicAdd(&g_cnt[dst[i]], 1);
}

__device__ __forceinline__ int warp_incl_scan(int v, int lane)
{
    #pragma unroll
    for (int off = 1; off < 32; off <<= 1) {
        int x = __shfl_up_sync(0xffffffffu, v, off);
        if (lane >= off) v += x;
    }
    return v;
}

__global__ void scan_local(int n4)
{
    __shared__ int wsum[8];
    const int t = threadIdx.x;
    const int lane = t & 31;
    const int w = t >> 5;
    int i = blockIdx.x * 256 + t;

    int4 v = make_int4(0, 0, 0, 0);
    if (i < n4) v = ((const int4*)g_cnt)[i];
    int tsum = v.x + v.y + v.z + v.w;
    int incl = warp_incl_scan(tsum, lane);
    if (lane == 31) wsum[w] = incl;
    __syncthreads();
    if (w == 0 && lane < 8) {
        int s = wsum[lane];
        #pragma unroll
        for (int off = 1; off < 8; off <<= 1) {
            int x = __shfl_up_sync(0xffu, s, off);
            if (lane >= off) s += x;
        }
        wsum[lane] = s;
    }
    __syncthreads();
    int pre = (w > 0) ? wsum[w - 1] : 0;
    if (i < n4) {
        int excl = pre + incl - tsum;
        int4 o;
        o.x = excl;
        o.y = o.x + v.x;
        o.z = o.y + v.y;
        o.w = o.z + v.z;
        ((int4*)g_start)[i] = o;
    }
    if (t == 255) g_bsum[blockIdx.x] = pre + incl;
}

__global__ void scan_sums(int nb)
{
    __shared__ int sh[64];
    int t = threadIdx.x;
    int own = (t < nb) ? g_bsum[t] : 0;
    sh[t] = own;
    __syncthreads();
    #pragma unroll
    for (int off = 1; off < 64; off <<= 1) {
        int v = (t >= off) ? sh[t - off] : 0;
        __syncthreads();
        sh[t] += v;
        __syncthreads();
    }
    if (t < nb) g_boff[t] = sh[t] - own;   // exclusive
}

// Scatter bumps g_start itself (acts as cursor). Post-condition:
// g_start[d] = local_start + deg.
__global__ void scatter_kernel(const int* __restrict__ src,
                               const int* __restrict__ dst, int E)
{
    int i = blockIdx.x * blockDim.x + threadIdx.x;
    if (i < E) {
        int d = dst[i];
        int pos = atomicAdd(&g_start[d], 1) + g_boff[d >> 10];
        g_esrc[pos] = src[i];
    }
}

// ---------------------------------------------------------------------------
// Fused attention: one warp per dst; software-pipelined edge loop (prefetch
// next edge's K/V during current edge's reduce/exp/FMA). No atomics.
// ---------------------------------------------------------------------------
__global__ __launch_bounds__(256)
void fused_edge_kernel(float* __restrict__ out, int n_dst)
{
    const int warp = (blockIdx.x * blockDim.x + threadIdx.x) >> 5;
    const int lane = threadIdx.x & 31;
    if (warp >= n_dst) return;
    const int d = warp;

    const int deg  = g_cnt[d];
    // g_start[d] was advanced by scatter to local_start + deg
    const int base = g_start[d] + g_boff[d >> 10] - deg;

    const float4* qp = (const float4*)(g_Q + (size_t)d * OUT_DIM);
    const float4 q0 = qp[lane * 2];
    const float4 q1 = qp[lane * 2 + 1];

    float S = 0.0f;
    float acc[8] = {0.f, 0.f, 0.f, 0.f, 0.f, 0.f, 0.f, 0.f};

    for (int cb = 0; cb < deg; cb += 32) {
        int n = min(32, deg - cb);
        int eidx = (lane < n) ? g_esrc[base + cb + lane] : 0;

        // prologue: load edge 0
        int s0 = __shfl_sync(0xffffffffu, eidx, 0);
        const float4* kp = (const float4*)(g_K + (size_t)s0 * OUT_DIM);
        const float4* vp = (const float4*)(g_V + (size_t)s0 * OUT_DIM);
        float4 k0 = kp[lane * 2], k1 = kp[lane * 2 + 1];
        float4 v0 = vp[lane * 2], v1 = vp[lane * 2 + 1];

        for (int j = 0; j < n; j++) {
            // prefetch next edge's K/V before the dependent compute chain
            float4 nk0, nk1, nv0, nv1;
            if (j + 1 < n) {
                int s1 = __shfl_sync(0xffffffffu, eidx, j + 1);
                const float4* kp1 = (const float4*)(g_K + (size_t)s1 * OUT_DIM);
                const float4* vp1 = (const float4*)(g_V + (size_t)s1 * OUT_DIM);
                nk0 = kp1[lane * 2]; nk1 = kp1[lane * 2 + 1];
                nv0 = vp1[lane * 2]; nv1 = vp1[lane * 2 + 1];
            } else {
                nk0 = k0; nk1 = k1; nv0 = v0; nv1 = v1;
            }

            float dot = k0.x * q0.x + k0.y * q0.y + k0.z * q0.z + k0.w * q0.w
                      + k1.x * q1.x + k1.y * q1.y + k1.z * q1.z + k1.w * q1.w;
            dot += __shfl_xor_sync(0xffffffffu, dot, 1);
            dot += __shfl_xor_sync(0xffffffffu, dot, 2);
            dot += __shfl_xor_sync(0xffffffffu, dot, 4);
            float e = __expf(dot * 0.125f);

            S += e;
            acc[0] = fmaf(e, v0.x, acc[0]);
            acc[1] = fmaf(e, v0.y, acc[1]);
            acc[2] = fmaf(e, v0.z, acc[2]);
            acc[3] = fmaf(e, v0.w, acc[3]);
            acc[4] = fmaf(e, v1.x, acc[4]);
            acc[5] = fmaf(e, v1.y, acc[5]);
            acc[6] = fmaf(e, v1.z, acc[6]);
            acc[7] = fmaf(e, v1.w, acc[7]);

            k0 = nk0; k1 = nk1; v0 = nv0; v1 = nv1;
        }
    }

    float inv = (deg > 0) ? (1.0f / S) : 0.0f;
    float4 o0 = make_float4(acc[0] * inv, acc[1] * inv, acc[2] * inv, acc[3] * inv);
    float4 o1 = make_float4(acc[4] * inv, acc[5] * inv, acc[6] * inv, acc[7] * inv);

    float4* op = (float4*)(out + (size_t)d * OUT_DIM);
    op[lane * 2]     = o0;
    op[lane * 2 + 1] = o1;
}

// ---------------------------------------------------------------------------
// Launch
// ---------------------------------------------------------------------------
extern "C" void kernel_launch(void* const* d_in, const int* in_sizes, int n_in,
                              void* d_out, int out_size)
{
    const float* h_src   = (const float*)d_in[0];
    const float* h_dst   = (const float*)d_in[1];
    const int*   src_idx = (const int*)  d_in[2];
    const int*   dst_idx = (const int*)  d_in[3];
    const float* Wq      = (const float*)d_in[4];
    const float* bq      = (const float*)d_in[5];
    const float* Wk      = (const float*)d_in[6];
    const float* bk      = (const float*)d_in[7];
    const float* Wv      = (const float*)d_in[8];
    const float* bv      = (const float*)d_in[9];

    const int n_src = in_sizes[0] / IN_DIM;
    const int n_dst = in_sizes[1] / IN_DIM;
    const int E     = in_sizes[2];

    float* out = (float*)d_out;

    float *pQ, *pK, *pV;
    int   *pcnt;
    cudaGetSymbolAddress((void**)&pQ, g_Q);
    cudaGetSymbolAddress((void**)&pK, g_K);
    cudaGetSymbolAddress((void**)&pV, g_V);
    cudaGetSymbolAddress((void**)&pcnt, g_cnt);

    const int SMEM_SINGLE = (2 * (128 * 36 + 64 * 36)) * 4;        // 55296
    const int SMEM_DUAL   = (2 * (128 * 36 + 2 * 64 * 36)) * 4;    // 73728
    cudaFuncSetAttribute(gemm_cpasync<false>,
                         cudaFuncAttributeMaxDynamicSharedMemorySize, SMEM_SINGLE);
    cudaFuncSetAttribute(gemm_cpasync<true>,
                         cudaFuncAttributeMaxDynamicSharedMemorySize, SMEM_DUAL);

    // ---- Projections ----
    {
        dim3 blk(256);
        dim3 gq((n_dst + 127) / 128, OUT_DIM / 64);
        dim3 gs((n_src + 127) / 128, OUT_DIM / 64);
        gemm_cpasync<false><<<gq, blk, SMEM_SINGLE>>>(
            h_dst, Wq, bq, pQ, nullptr, nullptr, nullptr, n_dst);
        gemm_cpasync<true><<<gs, blk, SMEM_DUAL>>>(
            h_src, Wk, bk, pK, Wv, bv, pV, n_src);
    }

    // ---- CSR build ----
    cudaMemsetAsync(pcnt, 0, sizeof(int) * MAX_DST);
    histogram_kernel<<<(E + 255) / 256, 256>>>(dst_idx, E);
    {
        int n4 = (n_dst + 3) / 4;
        int nb = (n4 + 255) / 256;
        scan_local<<<nb, 256>>>(n4);
        scan_sums<<<1, 64>>>(nb);
    }
    scatter_kernel<<<(E + 255) / 256, 256>>>(src_idx, dst_idx, E);

    // ---- Fused gather + softmax + aggregate ----
    {
        int blocks = (n_dst * 32 + 255) / 256;
        fused_edge_kernel<<<blocks, 256>>>(out, n_dst);
    }
}

// round 15
// speedup vs baseline: 1.0529x; 1.0529x over previous
#include <cuda_runtime.h>
#include <cuda_bf16.h>
#include <cstdint>
#include <math_constants.h>

// ---------------------------------------------------------------------------
// Problem constants
// ---------------------------------------------------------------------------
#define IN_DIM   256
#define OUT_DIM  256
#define NUM_HEADS 4
#define HEAD_DIM  64
#define MAX_SRC  100000
#define MAX_DST  50000
#define MAX_E    300000
#define KV_LD    512            // interleaved K|V row stride
#define NBLK_SCAN 64            // >= ceil(ceil(MAX_DST/4)/256) = 49

// ---------------------------------------------------------------------------
// Device-global scratch
// ---------------------------------------------------------------------------
__device__ float g_Q [(size_t)MAX_DST * OUT_DIM];
__device__ float g_KV[(size_t)MAX_SRC * KV_LD];   // [src][0:256)=K, [256:512)=V
__device__ int   g_cnt[MAX_DST];
__device__ int   g_start[MAX_DST];   // local excl scan; post-scatter = start+deg
__device__ int   g_bsum[NBLK_SCAN];
__device__ int   g_boff[NBLK_SCAN];
__device__ int   g_esrc[MAX_E];

// ---------------------------------------------------------------------------
// Helpers
// ---------------------------------------------------------------------------
__device__ __forceinline__ unsigned f2tf32(float f) {
    unsigned u;
    asm("cvt.rna.tf32.f32 %0, %1;" : "=r"(u) : "f"(f));
    return u;
}

__device__ __forceinline__ void mma_tf32(float c[4], const unsigned a[4],
                                         const unsigned b[2]) {
    asm volatile(
        "mma.sync.aligned.m16n8k8.row.col.f32.tf32.tf32.f32 "
        "{%0,%1,%2,%3}, {%4,%5,%6,%7}, {%8,%9}, {%0,%1,%2,%3};"
        : "+f"(c[0]), "+f"(c[1]), "+f"(c[2]), "+f"(c[3])
        : "r"(a[0]), "r"(a[1]), "r"(a[2]), "r"(a[3]), "r"(b[0]), "r"(b[1]));
}

__device__ __forceinline__ void cp16(unsigned dst, const void* src, int sz) {
    asm volatile("cp.async.cg.shared.global [%0], [%1], 16, %2;"
                 :: "r"(dst), "l"(src), "r"(sz));
}
__device__ __forceinline__ void cp_commit() {
    asm volatile("cp.async.commit_group;");
}
__device__ __forceinline__ void cp_wait_all() {
    asm volatile("cp.async.wait_group 0;");
}

// ---------------------------------------------------------------------------
// TF32 GEMM, cp.async double-buffered, optional dual output (K,V share A).
// R10/R12-proven shape: CTA 128(M) x 64(N), BK=32, 8 warps 4(M) x 2(N).
// ldc = output row stride (256 for Q, 512 for interleaved KV).
// ---------------------------------------------------------------------------
template<bool DUAL>
__global__ __launch_bounds__(256)
void gemm_cpasync(const float* __restrict__ A,
                  const float* __restrict__ W0, const float* __restrict__ b0,
                  float* __restrict__ C0,
                  const float* __restrict__ W1, const float* __restrict__ b1,
                  float* __restrict__ C1, int M, int ldc)
{
    extern __shared__ __align__(16) unsigned char smraw[];
    const int A_ELE   = 128 * 36;
    const int W_ELE   = 64 * 36;
    const int STG_ELE = A_ELE + (DUAL ? 2 : 1) * W_ELE;

    float*    smf = (float*)smraw;
    unsigned* smu = (unsigned*)smraw;
    const unsigned sm_u32 = (unsigned)__cvta_generic_to_shared(smraw);

    const int bm = blockIdx.x * 128;
    const int bn = blockIdx.y * 64;
    const int t    = threadIdx.x;
    const int warp = t >> 5;
    const int lane = t & 31;
    const int wm   = warp >> 1;
    const int wn   = warp & 1;
    const int g    = lane >> 2;
    const int tg   = lane & 3;

    int ar[4], ac[4];
    #pragma unroll
    for (int i = 0; i < 4; i++) { int idx = t + i * 256; ar[i] = idx >> 3; ac[i] = (idx & 7) * 4; }
    int wr[2], wc[2];
    #pragma unroll
    for (int i = 0; i < 2; i++) { int idx = t + i * 256; wr[i] = idx >> 3; wc[i] = (idx & 7) * 4; }

    float c0[2][4][4] = {};
    float c1[2][4][4] = {};

    auto loadA = [&](int kk, int st) {
        unsigned base = sm_u32 + (unsigned)(st * STG_ELE) * 4u;
        #pragma unroll
        for (int i = 0; i < 4; i++) {
            int row = bm + ar[i];
            const float* src = A + (size_t)(row < M ? row : (M - 1)) * IN_DIM + kk + ac[i];
            cp16(base + (unsigned)(ar[i] * 36 + ac[i]) * 4u, src, (row < M) ? 16 : 0);
        }
        cp_commit();
    };

    uint4 w0reg[2], w1reg[2];
    auto loadW = [&](int kk) {
        #pragma unroll
        for (int i = 0; i < 2; i++) {
            float4 v = *(const float4*)(W0 + (size_t)(bn + wr[i]) * IN_DIM + kk + wc[i]);
            w0reg[i] = make_uint4(f2tf32(v.x), f2tf32(v.y), f2tf32(v.z), f2tf32(v.w));
            if (DUAL) {
                float4 u = *(const float4*)(W1 + (size_t)(bn + wr[i]) * IN_DIM + kk + wc[i]);
                w1reg[i] = make_uint4(f2tf32(u.x), f2tf32(u.y), f2tf32(u.z), f2tf32(u.w));
            }
        }
    };
    auto storeW = [&](int st) {
        unsigned* p0 = smu + st * STG_ELE + A_ELE;
        #pragma unroll
        for (int i = 0; i < 2; i++)
            *(uint4*)(p0 + wr[i] * 36 + wc[i]) = w0reg[i];
        if (DUAL) {
            unsigned* p1 = p0 + W_ELE;
            #pragma unroll
            for (int i = 0; i < 2; i++)
                *(uint4*)(p1 + wr[i] * 36 + wc[i]) = w1reg[i];
        }
    };

    loadA(0, 0);
    loadW(0);
    storeW(0);
    cp_wait_all();
    __syncthreads();

    const int NSTG = IN_DIM / 32;   // 8
    for (int it = 0; it < NSTG; it++) {
        int cur = it & 1, nxt = cur ^ 1;
        if (it + 1 < NSTG) {
            loadA((it + 1) * 32, nxt);
            loadW((it + 1) * 32);
        }

        const float*    Af = smf + cur * STG_ELE;
        const unsigned* B0 = smu + cur * STG_ELE + A_ELE;
        const unsigned* B1 = B0 + W_ELE;
        #pragma unroll
        for (int ks = 0; ks < 32; ks += 8) {
            unsigned a[2][4], b0f[4][2], b1f[4][2];
            #pragma unroll
            for (int mi = 0; mi < 2; mi++) {
                int r = wm * 32 + mi * 16;
                a[mi][0] = f2tf32(Af[(r + g) * 36 + ks + tg]);
                a[mi][1] = f2tf32(Af[(r + g + 8) * 36 + ks + tg]);
                a[mi][2] = f2tf32(Af[(r + g) * 36 + ks + tg + 4]);
                a[mi][3] = f2tf32(Af[(r + g + 8) * 36 + ks + tg + 4]);
            }
            #pragma unroll
            for (int nj = 0; nj < 4; nj++) {
                int r = wn * 32 + nj * 8 + g;
                b0f[nj][0] = B0[r * 36 + ks + tg];
                b0f[nj][1] = B0[r * 36 + ks + tg + 4];
                if (DUAL) {
                    b1f[nj][0] = B1[r * 36 + ks + tg];
                    b1f[nj][1] = B1[r * 36 + ks + tg + 4];
                }
            }
            #pragma unroll
            for (int mi = 0; mi < 2; mi++)
                #pragma unroll
                for (int nj = 0; nj < 4; nj++) {
                    mma_tf32(c0[mi][nj], a[mi], b0f[nj]);
                    if (DUAL) mma_tf32(c1[mi][nj], a[mi], b1f[nj]);
                }
        }

        if (it + 1 < NSTG) storeW(nxt);
        cp_wait_all();
        __syncthreads();
    }

    #pragma unroll
    for (int mi = 0; mi < 2; mi++) {
        int row0 = bm + wm * 32 + mi * 16 + g;
        #pragma unroll
        for (int nj = 0; nj < 4; nj++) {
            int col = bn + wn * 32 + nj * 8 + 2 * tg;
            float bb0 = b0[col], bb1 = b0[col + 1];
            if (row0 < M) {
                C0[(size_t)row0 * ldc + col]     = c0[mi][nj][0] + bb0;
                C0[(size_t)row0 * ldc + col + 1] = c0[mi][nj][1] + bb1;
            }
            if (row0 + 8 < M) {
                C0[(size_t)(row0 + 8) * ldc + col]     = c0[mi][nj][2] + bb0;
                C0[(size_t)(row0 + 8) * ldc + col + 1] = c0[mi][nj][3] + bb1;
            }
            if (DUAL) {
                float db0 = b1[col], db1 = b1[col + 1];
                if (row0 < M) {
                    C1[(size_t)row0 * ldc + col]     = c1[mi][nj][0] + db0;
                    C1[(size_t)row0 * ldc + col + 1] = c1[mi][nj][1] + db1;
                }
                if (row0 + 8 < M) {
                    C1[(size_t)(row0 + 8) * ldc + col]     = c1[mi][nj][2] + db0;
                    C1[(size_t)(row0 + 8) * ldc + col + 1] = c1[mi][nj][3] + db1;
                }
            }
        }
    }
}

// ---------------------------------------------------------------------------
// CSR build
// ---------------------------------------------------------------------------
__global__ void histogram_kernel(const int* __restrict__ dst, int E)
{
    int i = blockIdx.x * blockDim.x + threadIdx.x;
    if (i < E) atomicAdd(&g_cnt[dst[i]], 1);
}

__device__ __forceinline__ int warp_incl_scan(int v, int lane)
{
    #pragma unroll
    for (int off = 1; off < 32; off <<= 1) {
        int x = __shfl_up_sync(0xffffffffu, v, off);
        if (lane >= off) v += x;
    }
    return v;
}

__global__ void scan_local(int n4)
{
    __shared__ int wsum[8];
    const int t = threadIdx.x;
    const int lane = t & 31;
    const int w = t >> 5;
    int i = blockIdx.x * 256 + t;

    int4 v = make_int4(0, 0, 0, 0);
    if (i < n4) v = ((const int4*)g_cnt)[i];
    int tsum = v.x + v.y + v.z + v.w;
    int incl = warp_incl_scan(tsum, lane);
    if (lane == 31) wsum[w] = incl;
    __syncthreads();
    if (w == 0 && lane < 8) {
        int s = wsum[lane];
        #pragma unroll
        for (int off = 1; off < 8; off <<= 1) {
            int x = __shfl_up_sync(0xffu, s, off);
            if (lane >= off) s += x;
        }
        wsum[lane] = s;
    }
    __syncthreads();
    int pre = (w > 0) ? wsum[w - 1] : 0;
    if (i < n4) {
        int excl = pre + incl - tsum;
        int4 o;
        o.x = excl;
        o.y = o.x + v.x;
        o.z = o.y + v.y;
        o.w = o.z + v.z;
        ((int4*)g_start)[i] = o;
    }
    if (t == 255) g_bsum[blockIdx.x] = pre + incl;
}

__global__ void scan_sums(int nb)
{
    __shared__ int sh[64];
    int t = threadIdx.x;
    int own = (t < nb) ? g_bsum[t] : 0;
    sh[t] = own;
    __syncthreads();
    #pragma unroll
    for (int off = 1; off < 64; off <<= 1) {
        int v = (t >= off) ? sh[t - off] : 0;
        __syncthreads();
        sh[t] += v;
        __syncthreads();
    }
    if (t < nb) g_boff[t] = sh[t] - own;   // exclusive
}

// Scatter bumps g_start itself (acts as cursor). Post: g_start[d]=start+deg.
__global__ void scatter_kernel(const int* __restrict__ src,
                               const int* __restrict__ dst, int E)
{
    int i = blockIdx.x * blockDim.x + threadIdx.x;
    if (i < E) {
        int d = dst[i];
        int pos = atomicAdd(&g_start[d], 1) + g_boff[d >> 10];
        g_esrc[pos] = src[i];
    }
}

// ---------------------------------------------------------------------------
// Fused attention (R12-proven simple loop): one warp per dst, chunked
// coalesced index prefetch + shfl broadcast. Interleaved KV reads.
// ---------------------------------------------------------------------------
__global__ __launch_bounds__(256)
void fused_edge_kernel(float* __restrict__ out, int n_dst)
{
    const int warp = (blockIdx.x * blockDim.x + threadIdx.x) >> 5;
    const int lane = threadIdx.x & 31;
    if (warp >= n_dst) return;
    const int d = warp;

    const int deg  = g_cnt[d];
    const int base = g_start[d] + g_boff[d >> 10] - deg;

    const float4* qp = (const float4*)(g_Q + (size_t)d * OUT_DIM);
    const float4 q0 = qp[lane * 2];
    const float4 q1 = qp[lane * 2 + 1];

    float S = 0.0f;
    float acc[8] = {0.f, 0.f, 0.f, 0.f, 0.f, 0.f, 0.f, 0.f};

    for (int cb = 0; cb < deg; cb += 32) {
        int n = min(32, deg - cb);
        int eidx = (lane < n) ? g_esrc[base + cb + lane] : 0;

        for (int j = 0; j < n; j++) {
            int s = __shfl_sync(0xffffffffu, eidx, j);

            const float4* kvp = (const float4*)(g_KV + (size_t)s * KV_LD);
            float4 k0 = kvp[lane * 2];
            float4 k1 = kvp[lane * 2 + 1];
            float4 v0 = kvp[64 + lane * 2];       // V starts at float 256
            float4 v1 = kvp[64 + lane * 2 + 1];

            float dot = k0.x * q0.x + k0.y * q0.y + k0.z * q0.z + k0.w * q0.w
                      + k1.x * q1.x + k1.y * q1.y + k1.z * q1.z + k1.w * q1.w;
            dot += __shfl_xor_sync(0xffffffffu, dot, 1);
            dot += __shfl_xor_sync(0xffffffffu, dot, 2);
            dot += __shfl_xor_sync(0xffffffffu, dot, 4);
            float e = __expf(dot * 0.125f);

            S += e;
            acc[0] = fmaf(e, v0.x, acc[0]);
            acc[1] = fmaf(e, v0.y, acc[1]);
            acc[2] = fmaf(e, v0.z, acc[2]);
            acc[3] = fmaf(e, v0.w, acc[3]);
            acc[4] = fmaf(e, v1.x, acc[4]);
            acc[5] = fmaf(e, v1.y, acc[5]);
            acc[6] = fmaf(e, v1.z, acc[6]);
            acc[7] = fmaf(e, v1.w, acc[7]);
        }
    }

    float inv = (deg > 0) ? (1.0f / S) : 0.0f;
    float4 o0 = make_float4(acc[0] * inv, acc[1] * inv, acc[2] * inv, acc[3] * inv);
    float4 o1 = make_float4(acc[4] * inv, acc[5] * inv, acc[6] * inv, acc[7] * inv);

    float4* op = (float4*)(out + (size_t)d * OUT_DIM);
    op[lane * 2]     = o0;
    op[lane * 2 + 1] = o1;
}

// ---------------------------------------------------------------------------
// Launch — CSR build FIRST (independent of GEMMs) so the fixed-offset ncu
// capture (-s 5 -c 1) lands on a GEMM instead of a 5 µs scan kernel.
// ---------------------------------------------------------------------------
extern "C" void kernel_launch(void* const* d_in, const int* in_sizes, int n_in,
                              void* d_out, int out_size)
{
    const float* h_src   = (const float*)d_in[0];
    const float* h_dst   = (const float*)d_in[1];
    const int*   src_idx = (const int*)  d_in[2];
    const int*   dst_idx = (const int*)  d_in[3];
    const float* Wq      = (const float*)d_in[4];
    const float* bq      = (const float*)d_in[5];
    const float* Wk      = (const float*)d_in[6];
    const float* bk      = (const float*)d_in[7];
    const float* Wv      = (const float*)d_in[8];
    const float* bv      = (const float*)d_in[9];

    const int n_src = in_sizes[0] / IN_DIM;
    const int n_dst = in_sizes[1] / IN_DIM;
    const int E     = in_sizes[2];

    float* out = (float*)d_out;

    float *pQ, *pKV;
    int   *pcnt;
    cudaGetSymbolAddress((void**)&pQ,  g_Q);
    cudaGetSymbolAddress((void**)&pKV, g_KV);
    cudaGetSymbolAddress((void**)&pcnt, g_cnt);

    const int SMEM_SINGLE = (2 * (128 * 36 + 64 * 36)) * 4;        // 55296
    const int SMEM_DUAL   = (2 * (128 * 36 + 2 * 64 * 36)) * 4;    // 73728
    cudaFuncSetAttribute(gemm_cpasync<false>,
                         cudaFuncAttributeMaxDynamicSharedMemorySize, SMEM_SINGLE);
    cudaFuncSetAttribute(gemm_cpasync<true>,
                         cudaFuncAttributeMaxDynamicSharedMemorySize, SMEM_DUAL);

    // ---- CSR build (launches 1..4 + memset) ----
    cudaMemsetAsync(pcnt, 0, sizeof(int) * MAX_DST);
    histogram_kernel<<<(E + 255) / 256, 256>>>(dst_idx, E);
    {
        int n4 = (n_dst + 3) / 4;
        int nb = (n4 + 255) / 256;
        scan_local<<<nb, 256>>>(n4);
        scan_sums<<<1, 64>>>(nb);
    }
    scatter_kernel<<<(E + 255) / 256, 256>>>(src_idx, dst_idx, E);

    // ---- Projections (launches 5..6 — ncu -s 5 samples here) ----
    {
        dim3 blk(256);
        dim3 gq((n_dst + 127) / 128, OUT_DIM / 64);
        dim3 gs((n_src + 127) / 128, OUT_DIM / 64);
        gemm_cpasync<false><<<gq, blk, SMEM_SINGLE>>>(
            h_dst, Wq, bq, pQ, nullptr, nullptr, nullptr, n_dst, OUT_DIM);
        gemm_cpasync<true><<<gs, blk, SMEM_DUAL>>>(
            h_src, Wk, bk, pKV, Wv, bv, pKV + OUT_DIM, n_src, KV_LD);
    }

    // ---- Fused gather + softmax + aggregate ----
    {
        int blocks = (n_dst * 32 + 255) / 256;
        fused_edge_kernel<<<blocks, 256>>>(out, n_dst);
    }
}

// round 16
// speedup vs baseline: 1.0598x; 1.0066x over previous
#include <cuda_runtime.h>
#include <cuda_bf16.h>
#include <cstdint>
#include <math_constants.h>

// ---------------------------------------------------------------------------
// Problem constants
// ---------------------------------------------------------------------------
#define IN_DIM   256
#define OUT_DIM  256
#define NUM_HEADS 4
#define HEAD_DIM  64
#define MAX_SRC  100000
#define MAX_DST  50000
#define MAX_E    300000
#define KV_LD    512            // interleaved K|V row stride
#define NBLK_SCAN 64            // >= ceil(ceil(MAX_DST/4)/256) = 49

// ---------------------------------------------------------------------------
// Device-global scratch
// ---------------------------------------------------------------------------
__device__ float g_Q [(size_t)MAX_DST * OUT_DIM];
__device__ float g_KV[(size_t)MAX_SRC * KV_LD];   // [src][0:256)=K, [256:512)=V
__device__ int   g_cnt[MAX_DST];
__device__ int   g_start[MAX_DST];   // local excl scan; post-scatter = start+deg
__device__ int   g_bsum[NBLK_SCAN];
__device__ int   g_boff[NBLK_SCAN];
__device__ int   g_esrc[MAX_E];

// ---------------------------------------------------------------------------
// Helpers
// ---------------------------------------------------------------------------
__device__ __forceinline__ unsigned f2tf32(float f) {
    unsigned u;
    asm("cvt.rna.tf32.f32 %0, %1;" : "=r"(u) : "f"(f));
    return u;
}

__device__ __forceinline__ void mma_tf32(float c[4], const unsigned a[4],
                                         const unsigned b[2]) {
    asm volatile(
        "mma.sync.aligned.m16n8k8.row.col.f32.tf32.tf32.f32 "
        "{%0,%1,%2,%3}, {%4,%5,%6,%7}, {%8,%9}, {%0,%1,%2,%3};"
        : "+f"(c[0]), "+f"(c[1]), "+f"(c[2]), "+f"(c[3])
        : "r"(a[0]), "r"(a[1]), "r"(a[2]), "r"(a[3]), "r"(b[0]), "r"(b[1]));
}

__device__ __forceinline__ void cp16(unsigned dst, const void* src, int sz) {
    asm volatile("cp.async.cg.shared.global [%0], [%1], 16, %2;"
                 :: "r"(dst), "l"(src), "r"(sz));
}
__device__ __forceinline__ void cp_commit() {
    asm volatile("cp.async.commit_group;");
}
__device__ __forceinline__ void cp_wait_all() {
    asm volatile("cp.async.wait_group 0;");
}

// ---------------------------------------------------------------------------
// TF32 GEMM, cp.async double-buffered, optional dual output (K,V share A).
// CTA 128(M) x 64(N), BK=32, 8 warps 4(M) x 2(N).
// GRID SWIZZLE: blockIdx.x = N-tile (fastest), blockIdx.y = M-tile, so the
// 4 N-tile CTAs sharing one A-slab are launch-adjacent -> A hits L2 3 of 4x.
// ---------------------------------------------------------------------------
template<bool DUAL>
__global__ __launch_bounds__(256)
void gemm_cpasync(const float* __restrict__ A,
                  const float* __restrict__ W0, const float* __restrict__ b0,
                  float* __restrict__ C0,
                  const float* __restrict__ W1, const float* __restrict__ b1,
                  float* __restrict__ C1, int M, int ldc)
{
    extern __shared__ __align__(16) unsigned char smraw[];
    const int A_ELE   = 128 * 36;
    const int W_ELE   = 64 * 36;
    const int STG_ELE = A_ELE + (DUAL ? 2 : 1) * W_ELE;

    float*    smf = (float*)smraw;
    unsigned* smu = (unsigned*)smraw;
    const unsigned sm_u32 = (unsigned)__cvta_generic_to_shared(smraw);

    const int bm = blockIdx.y * 128;      // swizzled: y = M-tile
    const int bn = blockIdx.x * 64;       // swizzled: x = N-tile (fastest)
    const int t    = threadIdx.x;
    const int warp = t >> 5;
    const int lane = t & 31;
    const int wm   = warp >> 1;
    const int wn   = warp & 1;
    const int g    = lane >> 2;
    const int tg   = lane & 3;

    int ar[4], ac[4];
    #pragma unroll
    for (int i = 0; i < 4; i++) { int idx = t + i * 256; ar[i] = idx >> 3; ac[i] = (idx & 7) * 4; }
    int wr[2], wc[2];
    #pragma unroll
    for (int i = 0; i < 2; i++) { int idx = t + i * 256; wr[i] = idx >> 3; wc[i] = (idx & 7) * 4; }

    float c0[2][4][4] = {};
    float c1[2][4][4] = {};

    auto loadA = [&](int kk, int st) {
        unsigned base = sm_u32 + (unsigned)(st * STG_ELE) * 4u;
        #pragma unroll
        for (int i = 0; i < 4; i++) {
            int row = bm + ar[i];
            const float* src = A + (size_t)(row < M ? row : (M - 1)) * IN_DIM + kk + ac[i];
            cp16(base + (unsigned)(ar[i] * 36 + ac[i]) * 4u, src, (row < M) ? 16 : 0);
        }
        cp_commit();
    };

    uint4 w0reg[2], w1reg[2];
    auto loadW = [&](int kk) {
        #pragma unroll
        for (int i = 0; i < 2; i++) {
            float4 v = *(const float4*)(W0 + (size_t)(bn + wr[i]) * IN_DIM + kk + wc[i]);
            w0reg[i] = make_uint4(f2tf32(v.x), f2tf32(v.y), f2tf32(v.z), f2tf32(v.w));
            if (DUAL) {
                float4 u = *(const float4*)(W1 + (size_t)(bn + wr[i]) * IN_DIM + kk + wc[i]);
                w1reg[i] = make_uint4(f2tf32(u.x), f2tf32(u.y), f2tf32(u.z), f2tf32(u.w));
            }
        }
    };
    auto storeW = [&](int st) {
        unsigned* p0 = smu + st * STG_ELE + A_ELE;
        #pragma unroll
        for (int i = 0; i < 2; i++)
            *(uint4*)(p0 + wr[i] * 36 + wc[i]) = w0reg[i];
        if (DUAL) {
            unsigned* p1 = p0 + W_ELE;
            #pragma unroll
            for (int i = 0; i < 2; i++)
                *(uint4*)(p1 + wr[i] * 36 + wc[i]) = w1reg[i];
        }
    };

    loadA(0, 0);
    loadW(0);
    storeW(0);
    cp_wait_all();
    __syncthreads();

    const int NSTG = IN_DIM / 32;   // 8
    for (int it = 0; it < NSTG; it++) {
        int cur = it & 1, nxt = cur ^ 1;
        if (it + 1 < NSTG) {
            loadA((it + 1) * 32, nxt);
            loadW((it + 1) * 32);
        }

        const float*    Af = smf + cur * STG_ELE;
        const unsigned* B0 = smu + cur * STG_ELE + A_ELE;
        const unsigned* B1 = B0 + W_ELE;
        #pragma unroll
        for (int ks = 0; ks < 32; ks += 8) {
            unsigned a[2][4], b0f[4][2], b1f[4][2];
            #pragma unroll
            for (int mi = 0; mi < 2; mi++) {
                int r = wm * 32 + mi * 16;
                a[mi][0] = f2tf32(Af[(r + g) * 36 + ks + tg]);
                a[mi][1] = f2tf32(Af[(r + g + 8) * 36 + ks + tg]);
                a[mi][2] = f2tf32(Af[(r + g) * 36 + ks + tg + 4]);
                a[mi][3] = f2tf32(Af[(r + g + 8) * 36 + ks + tg + 4]);
            }
            #pragma unroll
            for (int nj = 0; nj < 4; nj++) {
                int r = wn * 32 + nj * 8 + g;
                b0f[nj][0] = B0[r * 36 + ks + tg];
                b0f[nj][1] = B0[r * 36 + ks + tg + 4];
                if (DUAL) {
                    b1f[nj][0] = B1[r * 36 + ks + tg];
                    b1f[nj][1] = B1[r * 36 + ks + tg + 4];
                }
            }
            #pragma unroll
            for (int mi = 0; mi < 2; mi++)
                #pragma unroll
                for (int nj = 0; nj < 4; nj++) {
                    mma_tf32(c0[mi][nj], a[mi], b0f[nj]);
                    if (DUAL) mma_tf32(c1[mi][nj], a[mi], b1f[nj]);
                }
        }

        if (it + 1 < NSTG) storeW(nxt);
        cp_wait_all();
        __syncthreads();
    }

    #pragma unroll
    for (int mi = 0; mi < 2; mi++) {
        int row0 = bm + wm * 32 + mi * 16 + g;
        #pragma unroll
        for (int nj = 0; nj < 4; nj++) {
            int col = bn + wn * 32 + nj * 8 + 2 * tg;
            float bb0 = b0[col], bb1 = b0[col + 1];
            if (row0 < M) {
                C0[(size_t)row0 * ldc + col]     = c0[mi][nj][0] + bb0;
                C0[(size_t)row0 * ldc + col + 1] = c0[mi][nj][1] + bb1;
            }
            if (row0 + 8 < M) {
                C0[(size_t)(row0 + 8) * ldc + col]     = c0[mi][nj][2] + bb0;
                C0[(size_t)(row0 + 8) * ldc + col + 1] = c0[mi][nj][3] + bb1;
            }
            if (DUAL) {
                float db0 = b1[col], db1 = b1[col + 1];
                if (row0 < M) {
                    C1[(size_t)row0 * ldc + col]     = c1[mi][nj][0] + db0;
                    C1[(size_t)row0 * ldc + col + 1] = c1[mi][nj][1] + db1;
                }
                if (row0 + 8 < M) {
                    C1[(size_t)(row0 + 8) * ldc + col]     = c1[mi][nj][2] + db0;
                    C1[(size_t)(row0 + 8) * ldc + col + 1] = c1[mi][nj][3] + db1;
                }
            }
        }
    }
}

// ---------------------------------------------------------------------------
// CSR build
// ---------------------------------------------------------------------------
__global__ void histogram_kernel(const int* __restrict__ dst, int E)
{
    int i = blockIdx.x * blockDim.x + threadIdx.x;
    if (i < E) atomicAdd(&g_cnt[dst[i]], 1);
}

__device__ __forceinline__ int warp_incl_scan(int v, int lane)
{
    #pragma unroll
    for (int off = 1; off < 32; off <<= 1) {
        int x = __shfl_up_sync(0xffffffffu, v, off);
        if (lane >= off) v += x;
    }
    return v;
}

__global__ void scan_local(int n4)
{
    __shared__ int wsum[8];
    const int t = threadIdx.x;
    const int lane = t & 31;
    const int w = t >> 5;
    int i = blockIdx.x * 256 + t;

    int4 v = make_int4(0, 0, 0, 0);
    if (i < n4) v = ((const int4*)g_cnt)[i];
    int tsum = v.x + v.y + v.z + v.w;
    int incl = warp_incl_scan(tsum, lane);
    if (lane == 31) wsum[w] = incl;
    __syncthreads();
    if (w == 0 && lane < 8) {
        int s = wsum[lane];
        #pragma unroll
        for (int off = 1; off < 8; off <<= 1) {
            int x = __shfl_up_sync(0xffu, s, off);
            if (lane >= off) s += x;
        }
        wsum[lane] = s;
    }
    __syncthreads();
    int pre = (w > 0) ? wsum[w - 1] : 0;
    if (i < n4) {
        int excl = pre + incl - tsum;
        int4 o;
        o.x = excl;
        o.y = o.x + v.x;
        o.z = o.y + v.y;
        o.w = o.z + v.z;
        ((int4*)g_start)[i] = o;
    }
    if (t == 255) g_bsum[blockIdx.x] = pre + incl;
}

__global__ void scan_sums(int nb)
{
    __shared__ int sh[64];
    int t = threadIdx.x;
    int own = (t < nb) ? g_bsum[t] : 0;
    sh[t] = own;
    __syncthreads();
    #pragma unroll
    for (int off = 1; off < 64; off <<= 1) {
        int v = (t >= off) ? sh[t - off] : 0;
        __syncthreads();
        sh[t] += v;
        __syncthreads();
    }
    if (t < nb) g_boff[t] = sh[t] - own;   // exclusive
}

// Scatter bumps g_start itself (acts as cursor). Post: g_start[d]=start+deg.
__global__ void scatter_kernel(const int* __restrict__ src,
                               const int* __restrict__ dst, int E)
{
    int i = blockIdx.x * blockDim.x + threadIdx.x;
    if (i < E) {
        int d = dst[i];
        int pos = atomicAdd(&g_start[d], 1) + g_boff[d >> 10];
        g_esrc[pos] = src[i];
    }
}

// ---------------------------------------------------------------------------
// Fused attention (R12-proven simple loop): one warp per dst, chunked
// coalesced index prefetch + shfl broadcast. Interleaved KV reads.
// ---------------------------------------------------------------------------
__global__ __launch_bounds__(256)
void fused_edge_kernel(float* __restrict__ out, int n_dst)
{
    const int warp = (blockIdx.x * blockDim.x + threadIdx.x) >> 5;
    const int lane = threadIdx.x & 31;
    if (warp >= n_dst) return;
    const int d = warp;

    const int deg  = g_cnt[d];
    const int base = g_start[d] + g_boff[d >> 10] - deg;

    const float4* qp = (const float4*)(g_Q + (size_t)d * OUT_DIM);
    const float4 q0 = qp[lane * 2];
    const float4 q1 = qp[lane * 2 + 1];

    float S = 0.0f;
    float acc[8] = {0.f, 0.f, 0.f, 0.f, 0.f, 0.f, 0.f, 0.f};

    for (int cb = 0; cb < deg; cb += 32) {
        int n = min(32, deg - cb);
        int eidx = (lane < n) ? g_esrc[base + cb + lane] : 0;

        for (int j = 0; j < n; j++) {
            int s = __shfl_sync(0xffffffffu, eidx, j);

            const float4* kvp = (const float4*)(g_KV + (size_t)s * KV_LD);
            float4 k0 = kvp[lane * 2];
            float4 k1 = kvp[lane * 2 + 1];
            float4 v0 = kvp[64 + lane * 2];       // V starts at float 256
            float4 v1 = kvp[64 + lane * 2 + 1];

            float dot = k0.x * q0.x + k0.y * q0.y + k0.z * q0.z + k0.w * q0.w
                      + k1.x * q1.x + k1.y * q1.y + k1.z * q1.z + k1.w * q1.w;
            dot += __shfl_xor_sync(0xffffffffu, dot, 1);
            dot += __shfl_xor_sync(0xffffffffu, dot, 2);
            dot += __shfl_xor_sync(0xffffffffu, dot, 4);
            float e = __expf(dot * 0.125f);

            S += e;
            acc[0] = fmaf(e, v0.x, acc[0]);
            acc[1] = fmaf(e, v0.y, acc[1]);
            acc[2] = fmaf(e, v0.z, acc[2]);
            acc[3] = fmaf(e, v0.w, acc[3]);
            acc[4] = fmaf(e, v1.x, acc[4]);
            acc[5] = fmaf(e, v1.y, acc[5]);
            acc[6] = fmaf(e, v1.z, acc[6]);
            acc[7] = fmaf(e, v1.w, acc[7]);
        }
    }

    float inv = (deg > 0) ? (1.0f / S) : 0.0f;
    float4 o0 = make_float4(acc[0] * inv, acc[1] * inv, acc[2] * inv, acc[3] * inv);
    float4 o1 = make_float4(acc[4] * inv, acc[5] * inv, acc[6] * inv, acc[7] * inv);

    float4* op = (float4*)(out + (size_t)d * OUT_DIM);
    op[lane * 2]     = o0;
    op[lane * 2 + 1] = o1;
}

// ---------------------------------------------------------------------------
// Launch — ordered so the dual KV GEMM is graph node #5 (ncu's fixed sample
// point): memset(1) hist(2) scan_local(3) scan_sums(4) gemmKV(5) gemmQ(6)
// scatter(7) fused(8). All dependencies respected (scatter needs scans only;
// fused needs everything).
// ---------------------------------------------------------------------------
extern "C" void kernel_launch(void* const* d_in, const int* in_sizes, int n_in,
                              void* d_out, int out_size)
{
    const float* h_src   = (const float*)d_in[0];
    const float* h_dst   = (const float*)d_in[1];
    const int*   src_idx = (const int*)  d_in[2];
    const int*   dst_idx = (const int*)  d_in[3];
    const float* Wq      = (const float*)d_in[4];
    const float* bq      = (const float*)d_in[5];
    const float* Wk      = (const float*)d_in[6];
    const float* bk      = (const float*)d_in[7];
    const float* Wv      = (const float*)d_in[8];
    const float* bv      = (const float*)d_in[9];

    const int n_src = in_sizes[0] / IN_DIM;
    const int n_dst = in_sizes[1] / IN_DIM;
    const int E     = in_sizes[2];

    float* out = (float*)d_out;

    float *pQ, *pKV;
    int   *pcnt;
    cudaGetSymbolAddress((void**)&pQ,  g_Q);
    cudaGetSymbolAddress((void**)&pKV, g_KV);
    cudaGetSymbolAddress((void**)&pcnt, g_cnt);

    const int SMEM_SINGLE = (2 * (128 * 36 + 64 * 36)) * 4;        // 55296
    const int SMEM_DUAL   = (2 * (128 * 36 + 2 * 64 * 36)) * 4;    // 73728
    cudaFuncSetAttribute(gemm_cpasync<false>,
                         cudaFuncAttributeMaxDynamicSharedMemorySize, SMEM_SINGLE);
    cudaFuncSetAttribute(gemm_cpasync<true>,
                         cudaFuncAttributeMaxDynamicSharedMemorySize, SMEM_DUAL);

    // ---- CSR build part 1 (nodes 1..4) ----
    cudaMemsetAsync(pcnt, 0, sizeof(int) * MAX_DST);
    histogram_kernel<<<(E + 255) / 256, 256>>>(dst_idx, E);
    {
        int n4 = (n_dst + 3) / 4;
        int nb = (n4 + 255) / 256;
        scan_local<<<nb, 256>>>(n4);
        scan_sums<<<1, 64>>>(nb);
    }

    // ---- Projections (nodes 5..6; KV GEMM at ncu's sample point) ----
    {
        dim3 blk(256);
        dim3 gs(OUT_DIM / 64, (n_src + 127) / 128);   // x = N-tile (fastest)
        dim3 gq(OUT_DIM / 64, (n_dst + 127) / 128);
        gemm_cpasync<true><<<gs, blk, SMEM_DUAL>>>(
            h_src, Wk, bk, pKV, Wv, bv, pKV + OUT_DIM, n_src, KV_LD);
        gemm_cpasync<false><<<gq, blk, SMEM_SINGLE>>>(
            h_dst, Wq, bq, pQ, nullptr, nullptr, nullptr, n_dst, OUT_DIM);
    }

    // ---- CSR build part 2 (node 7) ----
    scatter_kernel<<<(E + 255) / 256, 256>>>(src_idx, dst_idx, E);

    // ---- Fused gather + softmax + aggregate (node 8) ----
    {
        int blocks = (n_dst * 32 + 255) / 256;
        fused_edge_kernel<<<blocks, 256>>>(out, n_dst);
    }
}